// round 11
// baseline (speedup 1.0000x reference)
#include <cuda_runtime.h>
#include <math.h>

// Problem constants
#define BB 4
#define MM 500   // rows (pred2)
#define NN 500   // cols (pred1)
#define CC 91
#define NPAD 512
#define FULLMASK 0xffffffffu
#define MARGIN 1e-4f

// Scratch (device globals; no allocation allowed)
__device__ float g_s1[BB * NN * CC];   // sigmoid(pred1_logits)
__device__ float g_s2[BB * MM * CC];   // sigmoid(pred2_logits)
__device__ __align__(16) float g_cost[BB * MM * NPAD]; // padded cost rows
__device__ int   g_map[BB * MM];       // row -> col assignment

__device__ __forceinline__ long long pack_rcu(float u32v, int row) {
    return (long long)(((unsigned long long)__float_as_uint(u32v) << 32) |
                       (unsigned)row);
}

// ---------------------------------------------------------------------------
// 1) sigmoids
// ---------------------------------------------------------------------------
__global__ void sigmoid_kernel(const float* __restrict__ l1,
                               const float* __restrict__ l2) {
    int idx = blockIdx.x * blockDim.x + threadIdx.x;
    const int n1 = BB * NN * CC;
    const int n2 = BB * MM * CC;
    if (idx < n1) {
        float x = l1[idx];
        g_s1[idx] = 1.0f / (1.0f + expf(-x));
    } else if (idx < n1 + n2) {
        float x = l2[idx - n1];
        g_s2[idx - n1] = 1.0f / (1.0f + expf(-x));
    }
}

// ---------------------------------------------------------------------------
// 2) cost matrix: cost[b][i][j] = 0.5*||c2_i - c1_j||2 + 0.5*max_c|s2-s1|
// ---------------------------------------------------------------------------
__global__ __launch_bounds__(1024) void cost_kernel(
        const float* __restrict__ p1_boxes,
        const float* __restrict__ p2_boxes) {
    const int b = blockIdx.z;
    const int i0 = blockIdx.y * 32;
    const int j0 = blockIdx.x * 32;

    __shared__ float s2t[32][CC];
    __shared__ float s1t[32][CC];
    __shared__ float b2x[32], b2y[32], b1x[32], b1y[32];

    const int tx = threadIdx.x;
    const int ty = threadIdx.y;
    const int tid = ty * 32 + tx;

    for (int idx = tid; idx < 32 * CC; idx += 1024) {
        int r = idx / CC, c = idx % CC;
        int gi = i0 + r;
        int gj = j0 + r;
        s2t[r][c] = (gi < MM) ? g_s2[(b * MM + gi) * CC + c] : 0.0f;
        s1t[r][c] = (gj < NN) ? g_s1[(b * NN + gj) * CC + c] : 0.0f;
    }
    if (ty == 0) {
        int gi = i0 + tx;
        if (gi < MM) {
            b2x[tx] = p2_boxes[(b * MM + gi) * 4 + 0];
            b2y[tx] = p2_boxes[(b * MM + gi) * 4 + 1];
        }
    } else if (ty == 1) {
        int gj = j0 + tx;
        if (gj < NN) {
            b1x[tx] = p1_boxes[(b * NN + gj) * 4 + 0];
            b1y[tx] = p1_boxes[(b * NN + gj) * 4 + 1];
        }
    }
    __syncthreads();

    const int i = i0 + ty;
    const int j = j0 + tx;
    if (i < MM) {
        if (j < NN) {
            float mx = 0.0f;
            #pragma unroll
            for (int c = 0; c < CC; c++) {
                mx = fmaxf(mx, fabsf(s2t[ty][c] - s1t[tx][c]));
            }
            float dx = __fadd_rn(b2x[ty], -b1x[tx]);
            float dy = __fadd_rn(b2y[ty], -b1y[tx]);
            float cd = __fsqrt_rn(__fadd_rn(__fmul_rn(dx, dx), __fmul_rn(dy, dy)));
            g_cost[(b * MM + i) * NPAD + j] =
                __fadd_rn(__fmul_rn(0.5f, cd), __fmul_rn(0.5f, mx));
        } else {
            g_cost[(b * MM + i) * NPAD + j] = 1e30f;  // padding
        }
    }
}

// ---------------------------------------------------------------------------
// 3) exact LSA: column reduction (exact duals, u == 0) + shortest-augmenting-
//    path Dijkstra for free rows. One warp per batch; lane L owns columns
//    [L*16, L*16+16).
//    Speculative pipelining: after REDUX identifies the approximate argmin
//    column, its matched row (predicted next scan row) is loaded and the
//    dd32-independent part of the gate (p = c - t) is computed in registers,
//    hiding row-load latency under selection. The gate stays conservative
//    (MARGIN >> all fp32/quantization error), and all selection/dual math
//    is exact fp64 identical to the round-8 passing kernel.
// ---------------------------------------------------------------------------
__global__ __launch_bounds__(32) void lsa_kernel() {
    const int b = blockIdx.x;
    const int lane = threadIdx.x;
    const double DINF = __longlong_as_double(0x7ff0000000000000LL);
    const float  FINF = __int_as_float(0x7f800000);
    const float  FNINF = __int_as_float(0xff800000);

    __shared__ double u64s[MM];
    __shared__ double v64s[NPAD];
    __shared__ double s64s[NPAD];
    __shared__ float u32s[MM];
    __shared__ __align__(16) float v32s[NPAD];
    __shared__ __align__(16) float tshared[NPAD];
    __shared__ __align__(16) unsigned keysh[NPAD];
    __shared__ __align__(8) long long rcu[NPAD];  // (u32bits<<32)|row4col
    __shared__ int paths[NPAD];
    __shared__ int col4rows[MM];
    __shared__ int SRs[MM];
    __shared__ int freeL[MM];
    __shared__ int sh_nf;

    for (int t = lane; t < NPAD; t += 32) {
        v64s[t] = 0.0; v32s[t] = 0.0f;
        rcu[t] = 0xffffffffLL;                 // row=-1, u=0
        if (t < MM) { u64s[t] = 0.0; u32s[t] = 0.0f; col4rows[t] = -1; }
    }
    const int base = lane * 16;
    unsigned validMask;
    {
        int nvalid = NN - base;
        if (nvalid < 0) nvalid = 0;
        if (nvalid > 16) nvalid = 16;
        validMask = (nvalid == 16) ? 0xffffu : ((1u << nvalid) - 1u);
    }
    __syncwarp();

    const float* costB = g_cost + (size_t)b * MM * NPAD;

    // ------------------- Phase A: column reduction --------------------------
    {
        float vmin[16];
        int imin[16];
        #pragma unroll
        for (int kk = 0; kk < 16; kk++) { vmin[kk] = FINF; imin[kk] = 0; }
        for (int i = 0; i < MM; i++) {
            const float* crow = costB + (size_t)i * NPAD + base;
            float4 ca = __ldg((const float4*)(crow + 0));
            float4 cb = __ldg((const float4*)(crow + 4));
            float4 cc_ = __ldg((const float4*)(crow + 8));
            float4 cd = __ldg((const float4*)(crow + 12));
            float c[16];
            c[0]=ca.x; c[1]=ca.y; c[2]=ca.z; c[3]=ca.w;
            c[4]=cb.x; c[5]=cb.y; c[6]=cb.z; c[7]=cb.w;
            c[8]=cc_.x; c[9]=cc_.y; c[10]=cc_.z; c[11]=cc_.w;
            c[12]=cd.x; c[13]=cd.y; c[14]=cd.z; c[15]=cd.w;
            #pragma unroll
            for (int kk = 0; kk < 16; kk++) {
                if (c[kk] < vmin[kk]) { vmin[kk] = c[kk]; imin[kk] = i; }
            }
        }
        #pragma unroll
        for (int kk = 0; kk < 16; kk++) {
            int j = base + kk;
            if ((validMask >> kk) & 1u) {
                v64s[j] = (double)vmin[kk];   // exact
                v32s[j] = vmin[kk];
                paths[j] = imin[kk];          // temp: argmin row per column
            }
        }
        __syncwarp();
        if (lane == 0) {
            for (int j = NN - 1; j >= 0; j--) {
                int i1 = paths[j];
                if (col4rows[i1] == -1) {
                    col4rows[i1] = j;
                    rcu[j] = (long long)(unsigned)i1;   // u=0 bits, row=i1
                }
            }
            int nf = 0;
            for (int i2 = 0; i2 < MM; i2++)
                if (col4rows[i2] < 0) freeL[nf++] = i2;
            sh_nf = nf;
        }
        __syncwarp();
    }
    const int nfree = sh_nf;
    __syncwarp();

    // --------- Phase B: Dijkstra augmentation for free rows -----------------
    for (int fidx = 0; fidx < nfree; fidx++) {
        const int cur = freeL[fidx];
        #pragma unroll
        for (int kk = 0; kk < 16; kk++) {
            tshared[base + kk] = ((validMask >> kk) & 1u) ? FINF : FNINF;
            keysh[base + kk] = 0xffffffffu;
            s64s[base + kk] = DINF;
        }
        unsigned scanned = 0;
        unsigned bkreg = 0xffffffffu;   // lane-local min key (register)
        unsigned pend = 0;              // bit of column removed last iteration
        float p[16];                    // speculative c - t for predicted row
        int specRow = -1;
        int jmSel = -1;                 // last selected column (for lazy minv)
        float minv32a = 0.0f;           // conservative (under-)estimate of minv
        int i = cur;
        float u32i = u32s[cur];
        int nSR = 0;
        int sink = -1;
        __syncwarp();

        while (true) {
            if (lane == 0) SRs[nSR] = i;
            nSR++;
            float dd32 = minv32a - u32i;
            float ndd32 = -dd32;
            const float* crow = costB + (size_t)i * NPAD + base;

            unsigned candMask = 0;
            if (i == specRow) {
                // fast gate: dd32-independent part precomputed last iteration
                #pragma unroll
                for (int kk = 0; kk < 16; kk++) {
                    if (p[kk] < ndd32) candMask |= (1u << kk);
                }
                candMask &= ~pend;
            } else {
                float4 ca = __ldg((const float4*)(crow + 0));
                float4 cb = __ldg((const float4*)(crow + 4));
                float4 cc_ = __ldg((const float4*)(crow + 8));
                float4 cd = __ldg((const float4*)(crow + 12));
                float4 ta = *(const float4*)(tshared + base + 0);
                float4 tb = *(const float4*)(tshared + base + 4);
                float4 tc = *(const float4*)(tshared + base + 8);
                float4 td = *(const float4*)(tshared + base + 12);
                if (ca.x + dd32 < ta.x) candMask |= 1u << 0;
                if (ca.y + dd32 < ta.y) candMask |= 1u << 1;
                if (ca.z + dd32 < ta.z) candMask |= 1u << 2;
                if (ca.w + dd32 < ta.w) candMask |= 1u << 3;
                if (cb.x + dd32 < tb.x) candMask |= 1u << 4;
                if (cb.y + dd32 < tb.y) candMask |= 1u << 5;
                if (cb.z + dd32 < tb.z) candMask |= 1u << 6;
                if (cb.w + dd32 < tb.w) candMask |= 1u << 7;
                if (cc_.x + dd32 < tc.x) candMask |= 1u << 8;
                if (cc_.y + dd32 < tc.y) candMask |= 1u << 9;
                if (cc_.z + dd32 < tc.z) candMask |= 1u << 10;
                if (cc_.w + dd32 < tc.w) candMask |= 1u << 11;
                if (cd.x + dd32 < td.x) candMask |= 1u << 12;
                if (cd.y + dd32 < td.y) candMask |= 1u << 13;
                if (cd.z + dd32 < td.z) candMask |= 1u << 14;
                if (cd.w + dd32 < td.w) candMask |= 1u << 15;
                candMask &= ~pend;
            }
            pend = 0;

            // exact fp64 updates for candidates only (lazy exact minv)
            if (candMask) {
                double minv = (jmSel < 0) ? 0.0 : s64s[jmSel];
                double dd = minv - u64s[i];
                do {
                    int kk = __ffs(candMask) - 1;
                    candMask &= candMask - 1;
                    int j = base + kk;
                    double r = ((double)__ldg(crow + kk) - v64s[j]) + dd;
                    if (r < s64s[j]) {
                        s64s[j] = r;
                        paths[j] = i;
                        float rf = (float)r;
                        unsigned ub = __float_as_uint(rf + 1.0f);
                        unsigned key = (ub & 0xfffffe00u) | (unsigned)j;
                        keysh[j] = key;
                        bkreg = min(bkreg, key);
                        tshared[j] = v32s[j] + (rf + MARGIN);
                    }
                } while (candMask);
            }

            // REDUX straight from the register min
            unsigned mk = __reduce_min_sync(FULLMASK, bkreg);
            if (mk == 0xffffffffu) { sink = -1; break; }  // defensive

            // approximate argmin column: LDS.64 gives (predicted row, its u32)
            int jm_a = (int)(mk & 0x1ffu);
            long long pr = rcu[jm_a];
            int r4c_a = (int)pr;
            unsigned ub_a = (unsigned)(((unsigned long long)pr) >> 32);

            // speculative load of predicted next row; precompute p = c - t
            if (r4c_a >= 0) {
                const float* nrow = costB + (size_t)r4c_a * NPAD + base;
                float4 na = __ldg((const float4*)(nrow + 0));
                float4 nb = __ldg((const float4*)(nrow + 4));
                float4 nc = __ldg((const float4*)(nrow + 8));
                float4 nd = __ldg((const float4*)(nrow + 12));
                float4 sa = *(const float4*)(tshared + base + 0);
                float4 sb = *(const float4*)(tshared + base + 4);
                float4 sc = *(const float4*)(tshared + base + 8);
                float4 sd = *(const float4*)(tshared + base + 12);
                p[0]  = na.x - sa.x; p[1]  = na.y - sa.y;
                p[2]  = na.z - sa.z; p[3]  = na.w - sa.w;
                p[4]  = nb.x - sb.x; p[5]  = nb.y - sb.y;
                p[6]  = nb.z - sb.z; p[7]  = nb.w - sb.w;
                p[8]  = nc.x - sc.x; p[9]  = nc.y - sc.y;
                p[10] = nc.z - sc.z; p[11] = nc.w - sc.w;
                p[12] = nd.x - sd.x; p[13] = nd.y - sd.y;
                p[14] = nd.z - sd.z; p[15] = nd.w - sd.w;
            }

            // threshold window (covers 9-bit key quantization + fp32 error)
            float dec = __uint_as_float(mk & 0xfffffe00u);
            unsigned thrKey = (__float_as_uint(dec + 1e-3f) & 0xfffffe00u) | 0x1ffu;

            unsigned resMask = 0;
            if (bkreg <= thrKey) {
                uint4 k0 = *(const uint4*)(keysh + base + 0);
                uint4 k1 = *(const uint4*)(keysh + base + 4);
                uint4 k2 = *(const uint4*)(keysh + base + 8);
                uint4 k3 = *(const uint4*)(keysh + base + 12);
                if (k0.x <= thrKey) resMask |= 1u << 0;
                if (k0.y <= thrKey) resMask |= 1u << 1;
                if (k0.z <= thrKey) resMask |= 1u << 2;
                if (k0.w <= thrKey) resMask |= 1u << 3;
                if (k1.x <= thrKey) resMask |= 1u << 4;
                if (k1.y <= thrKey) resMask |= 1u << 5;
                if (k1.z <= thrKey) resMask |= 1u << 6;
                if (k1.w <= thrKey) resMask |= 1u << 7;
                if (k2.x <= thrKey) resMask |= 1u << 8;
                if (k2.y <= thrKey) resMask |= 1u << 9;
                if (k2.z <= thrKey) resMask |= 1u << 10;
                if (k2.w <= thrKey) resMask |= 1u << 11;
                if (k3.x <= thrKey) resMask |= 1u << 12;
                if (k3.y <= thrKey) resMask |= 1u << 13;
                if (k3.z <= thrKey) resMask |= 1u << 14;
                if (k3.w <= thrKey) resMask |= 1u << 15;
            }

            unsigned bal1 = __ballot_sync(FULLMASK, resMask != 0);
            unsigned balM = __ballot_sync(FULLMASK, __popc(resMask) > 1);
            int jm;
            int r4c;
            unsigned ubx;
            if (balM == 0 && __popc(bal1) == 1) {
                // fast path: unique window candidate == approximate argmin
                jm = jm_a;
                r4c = r4c_a;
                ubx = ub_a;
            } else {
                // slow path: exact fp64 resolution (first-index tie-break)
                double bestV = DINF;
                int bestJ = 0x7fffffff;
                unsigned rm = resMask;
                while (rm) {
                    int kk = __ffs(rm) - 1;
                    rm &= rm - 1;
                    int j = base + kk;
                    double sv = s64s[j];
                    if (sv < bestV) { bestV = sv; bestJ = j; }  // ascending j
                }
                #pragma unroll
                for (int off = 16; off > 0; off >>= 1) {
                    double ov = __shfl_down_sync(FULLMASK, bestV, off);
                    int    oj = __shfl_down_sync(FULLMASK, bestJ, off);
                    if (ov < bestV || (ov == bestV && oj < bestJ)) { bestV = ov; bestJ = oj; }
                }
                jm = __shfl_sync(FULLMASK, bestJ, 0);
                if (jm > 0x1ff) { sink = -1; break; }   // defensive
                long long pr2 = rcu[jm];
                r4c = (int)pr2;
                ubx = (unsigned)(((unsigned long long)pr2) >> 32);
            }
            minv32a = dec - 1.0f;   // conservative underestimate (gate only)
            jmSel = jm;
            // remove column jm (owner lane) + recompute its register min
            if (lane == (jm >> 4)) {
                int kk = jm & 15;
                scanned |= (1u << kk);
                pend = (1u << kk);
                tshared[jm] = FNINF;
                keysh[jm] = 0xffffffffu;
                uint4 r0 = *(const uint4*)(keysh + base + 0);
                uint4 r1 = *(const uint4*)(keysh + base + 4);
                uint4 r2 = *(const uint4*)(keysh + base + 8);
                uint4 r3 = *(const uint4*)(keysh + base + 12);
                bkreg = min(min(min(min(r0.x, r0.y), min(r0.z, r0.w)),
                                min(min(r1.x, r1.y), min(r1.z, r1.w))),
                            min(min(min(r2.x, r2.y), min(r2.z, r2.w)),
                                min(min(r3.x, r3.y), min(r3.z, r3.w))));
            }
            if (r4c < 0) { sink = jm; break; }
            specRow = (jm == jm_a && r4c_a >= 0) ? r4c_a : -1;
            i = r4c;
            u32i = __uint_as_float(ubx);
        }
        __syncwarp();
        if (sink < 0) continue;       // defensive

        // dual updates (exact fp64) + rcu refresh for scanned matched columns
        const double minvF = s64s[sink];
        for (int s = lane; s < nSR; s += 32) {
            int row = SRs[s];
            double nu = u64s[row] +
                        ((s == 0) ? minvF : (minvF - s64s[col4rows[row]]));
            u64s[row] = nu;
            float nu32 = (float)nu;
            u32s[row] = nu32;
            if (s > 0) {
                rcu[col4rows[row]] = pack_rcu(nu32, row);
            }
        }
        {
            unsigned sm2 = scanned;
            while (sm2) {
                int kk = __ffs(sm2) - 1;
                sm2 &= sm2 - 1;
                int j = base + kk;
                double nv = v64s[j] - (minvF - s64s[j]);
                v64s[j] = nv;
                v32s[j] = (float)nv;
            }
        }
        __syncwarp();
        // augment along alternating path; keep rcu consistent
        if (lane == 0) {
            int j = sink;
            while (true) {
                int ii = paths[j];
                rcu[j] = pack_rcu(u32s[ii], ii);
                int t = col4rows[ii];
                col4rows[ii] = j;
                j = t;
                if (ii == cur) break;
            }
        }
        __syncwarp();
    }

    for (int t = lane; t < MM; t += 32) g_map[b * MM + t] = col4rows[t];
}

// ---------------------------------------------------------------------------
// 4) extrapolation + output write
// ---------------------------------------------------------------------------
__global__ void extrap_kernel(const float* __restrict__ p1_boxes,
                              const float* __restrict__ p1_logits,
                              const float* __restrict__ p2_boxes,
                              const float* __restrict__ p2_logits,
                              const float* __restrict__ toff,
                              float* __restrict__ out) {
    int idx = blockIdx.x * blockDim.x + threadIdx.x;
    const int boxTotal = BB * MM * 4;
    const int logTotal = BB * MM * CC;
    if (idx < boxTotal) {
        int d = idx & 3;
        int bi = idx >> 2;
        int b = bi / MM;
        float first  = toff[b * 3 + 1] - toff[b * 3 + 0];
        float second = toff[b * 3 + 2] - toff[b * 3 + 1];
        float factor = second / first;
        int mcol = g_map[bi];
        float b2 = p2_boxes[idx];
        float c1 = p1_boxes[(b * NN + mcol) * 4 + d];
        float val = b2 + (b2 - c1) * factor;
        if (d >= 2) val = fmaxf(val, 0.0f);
        out[idx] = val;
    } else if (idx < boxTotal + logTotal) {
        int t = idx - boxTotal;
        int c = t % CC;
        int bi = t / CC;
        int b = bi / MM;
        int mcol = g_map[bi];
        float l2 = p2_logits[t];
        float l1 = p1_logits[(b * NN + mcol) * CC + c];
        out[idx] = 0.5f * (l2 + l1);
    }
}

// ---------------------------------------------------------------------------
extern "C" void kernel_launch(void* const* d_in, const int* in_sizes, int n_in,
                              void* d_out, int out_size) {
    const float* p1_boxes  = (const float*)d_in[0];
    const float* p1_logits = (const float*)d_in[1];
    const float* p2_boxes  = (const float*)d_in[2];
    const float* p2_logits = (const float*)d_in[3];
    const float* toff      = (const float*)d_in[4];
    float* out = (float*)d_out;

    {
        int total = BB * NN * CC + BB * MM * CC;
        int threads = 256;
        int blocks = (total + threads - 1) / threads;
        sigmoid_kernel<<<blocks, threads>>>(p1_logits, p2_logits);
    }
    {
        dim3 grid(NPAD / 32, (MM + 31) / 32, BB);
        dim3 block(32, 32);
        cost_kernel<<<grid, block>>>(p1_boxes, p2_boxes);
    }
    lsa_kernel<<<BB, 32>>>();
    {
        int total = BB * MM * 4 + BB * MM * CC;
        int threads = 256;
        int blocks = (total + threads - 1) / threads;
        extrap_kernel<<<blocks, threads>>>(p1_boxes, p1_logits, p2_boxes,
                                           p2_logits, toff, out);
    }
}

// round 12
// speedup vs baseline: 1.1464x; 1.1464x over previous
#include <cuda_runtime.h>
#include <math.h>

// Problem constants
#define BB 4
#define MM 500   // rows (pred2)
#define NN 500   // cols (pred1)
#define CC 91
#define NPAD 512
#define FULLMASK 0xffffffffu
#define MARGIN 1e-4f

// Scratch (device globals; no allocation allowed)
__device__ float g_s1[BB * NN * CC];   // sigmoid(pred1_logits)
__device__ float g_s2[BB * MM * CC];   // sigmoid(pred2_logits)
__device__ __align__(16) float g_cost[BB * MM * NPAD]; // padded cost rows
__device__ int   g_map[BB * MM];       // row -> col assignment

// ---------------------------------------------------------------------------
// 1) sigmoids
// ---------------------------------------------------------------------------
__global__ void sigmoid_kernel(const float* __restrict__ l1,
                               const float* __restrict__ l2) {
    int idx = blockIdx.x * blockDim.x + threadIdx.x;
    const int n1 = BB * NN * CC;
    const int n2 = BB * MM * CC;
    if (idx < n1) {
        float x = l1[idx];
        g_s1[idx] = 1.0f / (1.0f + expf(-x));
    } else if (idx < n1 + n2) {
        float x = l2[idx - n1];
        g_s2[idx - n1] = 1.0f / (1.0f + expf(-x));
    }
}

// ---------------------------------------------------------------------------
// 2) cost matrix: cost[b][i][j] = 0.5*||c2_i - c1_j||2 + 0.5*max_c|s2-s1|
// ---------------------------------------------------------------------------
__global__ __launch_bounds__(1024) void cost_kernel(
        const float* __restrict__ p1_boxes,
        const float* __restrict__ p2_boxes) {
    const int b = blockIdx.z;
    const int i0 = blockIdx.y * 32;
    const int j0 = blockIdx.x * 32;

    __shared__ float s2t[32][CC];
    __shared__ float s1t[32][CC];
    __shared__ float b2x[32], b2y[32], b1x[32], b1y[32];

    const int tx = threadIdx.x;
    const int ty = threadIdx.y;
    const int tid = ty * 32 + tx;

    for (int idx = tid; idx < 32 * CC; idx += 1024) {
        int r = idx / CC, c = idx % CC;
        int gi = i0 + r;
        int gj = j0 + r;
        s2t[r][c] = (gi < MM) ? g_s2[(b * MM + gi) * CC + c] : 0.0f;
        s1t[r][c] = (gj < NN) ? g_s1[(b * NN + gj) * CC + c] : 0.0f;
    }
    if (ty == 0) {
        int gi = i0 + tx;
        if (gi < MM) {
            b2x[tx] = p2_boxes[(b * MM + gi) * 4 + 0];
            b2y[tx] = p2_boxes[(b * MM + gi) * 4 + 1];
        }
    } else if (ty == 1) {
        int gj = j0 + tx;
        if (gj < NN) {
            b1x[tx] = p1_boxes[(b * NN + gj) * 4 + 0];
            b1y[tx] = p1_boxes[(b * NN + gj) * 4 + 1];
        }
    }
    __syncthreads();

    const int i = i0 + ty;
    const int j = j0 + tx;
    if (i < MM) {
        if (j < NN) {
            float mx = 0.0f;
            #pragma unroll
            for (int c = 0; c < CC; c++) {
                mx = fmaxf(mx, fabsf(s2t[ty][c] - s1t[tx][c]));
            }
            float dx = __fadd_rn(b2x[ty], -b1x[tx]);
            float dy = __fadd_rn(b2y[ty], -b1y[tx]);
            float cd = __fsqrt_rn(__fadd_rn(__fmul_rn(dx, dx), __fmul_rn(dy, dy)));
            g_cost[(b * MM + i) * NPAD + j] =
                __fadd_rn(__fmul_rn(0.5f, cd), __fmul_rn(0.5f, mx));
        } else {
            g_cost[(b * MM + i) * NPAD + j] = 1e30f;  // padding
        }
    }
}

// ---------------------------------------------------------------------------
// 3) exact LSA: column reduction (exact duals, u == 0) + shortest-augmenting-
//    path Dijkstra for free rows, using the register-resident-key inner loop
//    (the measured-fastest per-iteration variant). One warp per batch; lane L
//    owns columns [L*16, L*16+16).
//    fp32 margin-pruned sweep; fp64 exact updates only on candidates;
//    packed-key REDUX gives approximate argmin early -> prefetch next row;
//    exact fp64 resolution within the threshold window (first-index ties).
// ---------------------------------------------------------------------------
__global__ __launch_bounds__(32) void lsa_kernel() {
    const int b = blockIdx.x;
    const int lane = threadIdx.x;
    const double DINF = __longlong_as_double(0x7ff0000000000000LL);
    const float  FINF = __int_as_float(0x7f800000);

    __shared__ double u64s[MM];
    __shared__ double v64s[NPAD];
    __shared__ double s64s[NPAD];
    __shared__ float u32s[MM];
    __shared__ __align__(16) float v32s[NPAD];
    __shared__ __align__(16) float s32s[NPAD];
    __shared__ int paths[NPAD];
    __shared__ int col4rows[MM];
    __shared__ int row4cols[NPAD];
    __shared__ int SRs[MM];
    __shared__ int freeL[MM];
    __shared__ int sh_nf;

    for (int t = lane; t < NPAD; t += 32) {
        v64s[t] = 0.0; v32s[t] = 0.0f; row4cols[t] = -1;
        if (t < MM) { u64s[t] = 0.0; u32s[t] = 0.0f; col4rows[t] = -1; }
    }
    const int base = lane * 16;
    unsigned validMask;
    {
        int nvalid = NN - base;
        if (nvalid < 0) nvalid = 0;
        if (nvalid > 16) nvalid = 16;
        validMask = (nvalid == 16) ? 0xffffu : ((1u << nvalid) - 1u);
    }
    __syncwarp();

    const float* costB = g_cost + (size_t)b * MM * NPAD;

    // ------------------- Phase A: column reduction --------------------------
    {
        float vmin[16];
        int imin[16];
        #pragma unroll
        for (int kk = 0; kk < 16; kk++) { vmin[kk] = FINF; imin[kk] = 0; }
        for (int i = 0; i < MM; i++) {
            const float* crow = costB + (size_t)i * NPAD + base;
            float4 ca = __ldg((const float4*)(crow + 0));
            float4 cb = __ldg((const float4*)(crow + 4));
            float4 cc_ = __ldg((const float4*)(crow + 8));
            float4 cd = __ldg((const float4*)(crow + 12));
            float c[16];
            c[0]=ca.x; c[1]=ca.y; c[2]=ca.z; c[3]=ca.w;
            c[4]=cb.x; c[5]=cb.y; c[6]=cb.z; c[7]=cb.w;
            c[8]=cc_.x; c[9]=cc_.y; c[10]=cc_.z; c[11]=cc_.w;
            c[12]=cd.x; c[13]=cd.y; c[14]=cd.z; c[15]=cd.w;
            #pragma unroll
            for (int kk = 0; kk < 16; kk++) {
                if (c[kk] < vmin[kk]) { vmin[kk] = c[kk]; imin[kk] = i; }
            }
        }
        #pragma unroll
        for (int kk = 0; kk < 16; kk++) {
            int j = base + kk;
            if ((validMask >> kk) & 1u) {
                v64s[j] = (double)vmin[kk];   // exact
                v32s[j] = vmin[kk];
                paths[j] = imin[kk];          // temp: argmin row per column
            }
        }
        __syncwarp();
        if (lane == 0) {
            for (int j = NN - 1; j >= 0; j--) {
                int i1 = paths[j];
                if (col4rows[i1] == -1) {
                    col4rows[i1] = j;
                    row4cols[j] = i1;
                }
            }
            int nf = 0;
            for (int i2 = 0; i2 < MM; i2++)
                if (col4rows[i2] < 0) freeL[nf++] = i2;
            sh_nf = nf;
        }
        __syncwarp();
    }
    const int nfree = sh_nf;
    __syncwarp();

    // ------ Phase B: Dijkstra rounds (register-resident-key inner loop) -----
    for (int fidx = 0; fidx < nfree; fidx++) {
        const int cur = freeL[fidx];
        #pragma unroll
        for (int kk = 0; kk < 16; kk++) {
            int j = base + kk;
            s64s[j] = DINF;
            s32s[j] = FINF;
        }
        unsigned rem = validMask;
        unsigned scanned = 0;
        double minv = 0.0;
        float minv32 = 0.0f;
        int i = cur;
        int nSR = 0;
        int sink = -1;
        __syncwarp();

        while (true) {
            if (lane == 0) SRs[nSR] = i;
            nSR++;
            float dd32 = minv32 - u32s[i];
            const float* crow = costB + (size_t)i * NPAD + base;

            float4 c4[4];
            c4[0] = __ldg((const float4*)(crow + 0));
            c4[1] = __ldg((const float4*)(crow + 4));
            c4[2] = __ldg((const float4*)(crow + 8));
            c4[3] = __ldg((const float4*)(crow + 12));

            // fp32 sweep over owned columns; build candidate mask + packed key
            float se[16];
            unsigned candMask = 0;
            unsigned bestKey = 0xffffffffu;
            #pragma unroll
            for (int q = 0; q < 4; q++) {
                float4 vv = *(const float4*)(v32s + base + q * 4);
                float4 sv = *(const float4*)(s32s + base + q * 4);
                float cA[4] = {c4[q].x, c4[q].y, c4[q].z, c4[q].w};
                float vA[4] = {vv.x, vv.y, vv.z, vv.w};
                float sA[4] = {sv.x, sv.y, sv.z, sv.w};
                #pragma unroll
                for (int e = 0; e < 4; e++) {
                    int kk = q * 4 + e;
                    float r = (cA[e] - vA[e]) + dd32;
                    bool remb = (rem >> kk) & 1u;
                    bool cand = remb && (r < sA[e] + MARGIN);
                    if (cand) candMask |= (1u << kk);
                    float s_eff = cand ? fminf(sA[e], r) : sA[e];
                    se[kk] = s_eff;
                    unsigned ub = __float_as_uint(s_eff);
                    unsigned tkey = ub ^ (((unsigned)((int)ub >> 31)) | 0x80000000u);
                    unsigned key = (tkey & 0xfffffe00u) | (unsigned)(base + kk);
                    bestKey = min(bestKey, key);
                }
            }
            // exact fp64 updates for candidates only
            if (candMask) {
                double dd = minv - u64s[i];
                do {
                    int kk = __ffs(candMask) - 1;
                    candMask &= candMask - 1;
                    int j = base + kk;
                    double c64 = (double)__ldg(crow + kk);
                    double r = (c64 - v64s[j]) + dd;
                    if (r < s64s[j]) {
                        s64s[j] = r;
                        float rf = (float)r;
                        s32s[j] = rf;
                        paths[j] = i;
                        unsigned ub = __float_as_uint(rf);
                        unsigned tkey = ub ^ (((unsigned)((int)ub >> 31)) | 0x80000000u);
                        unsigned key = (tkey & 0xfffffe00u) | (unsigned)j;
                        bestKey = min(bestKey, key);
                    }
                } while (candMask);
            }
            // one REDUX: approximate min value + approximate argmin column
            unsigned mk = __reduce_min_sync(FULLMASK, bestKey);
            int jm_a = (int)(mk & 0x1ffu);
            unsigned tval = mk & 0xfffffe00u;
            float m32 = (tval & 0x80000000u) ? __uint_as_float(tval & 0x7fffffffu)
                                             : __uint_as_float(~tval);
            // speculative prefetch of the likely next row (own segment)
            int i_next = row4cols[jm_a];
            if (i_next >= 0) {
                const float* pf = costB + (size_t)i_next * NPAD + base;
                asm volatile("prefetch.global.L1 [%0];" :: "l"(pf));
            }
            // exact resolution among columns within threshold
            float thr = fmaf(6.2e-5f, fabsf(m32), m32 + MARGIN);
            unsigned resMask = 0;
            #pragma unroll
            for (int kk = 0; kk < 16; kk++) {
                if (se[kk] <= thr) resMask |= (1u << kk);
            }
            resMask &= rem;
            double bestV = DINF;
            int bestJ = 0x7fffffff;
            while (resMask) {
                int kk = __ffs(resMask) - 1;
                resMask &= resMask - 1;
                int j = base + kk;
                double sv = s64s[j];
                if (sv < bestV) { bestV = sv; bestJ = j; }  // ascending j
            }
            unsigned bal = __ballot_sync(FULLMASK, bestJ != 0x7fffffff);
            int jm;
            if (__popc(bal) == 1) {
                int src = __ffs(bal) - 1;
                minv = __shfl_sync(FULLMASK, bestV, src);
                jm   = __shfl_sync(FULLMASK, bestJ, src);
            } else {
                #pragma unroll
                for (int off = 16; off > 0; off >>= 1) {
                    double ov = __shfl_down_sync(FULLMASK, bestV, off);
                    int    oj = __shfl_down_sync(FULLMASK, bestJ, off);
                    if (ov < bestV || (ov == bestV && oj < bestJ)) { bestV = ov; bestJ = oj; }
                }
                minv = __shfl_sync(FULLMASK, bestV, 0);
                jm   = __shfl_sync(FULLMASK, bestJ, 0);
            }
            if (jm > 0x1ff) { sink = -1; break; }   // defensive
            minv32 = (float)minv;
            // remove column jm
            if (lane == (jm >> 4)) {
                rem &= ~(1u << (jm & 15));
                scanned |= (1u << (jm & 15));
                s32s[jm] = FINF;
            }
            int r4c = row4cols[jm];   // shared broadcast
            if (r4c < 0) { sink = jm; break; }
            i = r4c;
        }
        __syncwarp();
        if (sink < 0) continue;       // defensive (never taken in valid runs)

        // dual updates (exact fp64)
        for (int s = lane; s < nSR; s += 32) {
            int row = SRs[s];
            double nu = u64s[row] +
                        ((s == 0) ? minv : (minv - s64s[col4rows[row]]));
            u64s[row] = nu;
            u32s[row] = (float)nu;
        }
        {
            unsigned sm2 = scanned;
            while (sm2) {
                int kk = __ffs(sm2) - 1;
                sm2 &= sm2 - 1;
                int j = base + kk;
                double nv = v64s[j] - (minv - s64s[j]);
                v64s[j] = nv;
                v32s[j] = (float)nv;
            }
        }
        __syncwarp();
        if (lane == 0) {
            int j = sink;
            while (true) {
                int ii = paths[j];
                row4cols[j] = ii;
                int t = col4rows[ii];
                col4rows[ii] = j;
                j = t;
                if (ii == cur) break;
            }
        }
        __syncwarp();
    }

    for (int t = lane; t < MM; t += 32) g_map[b * MM + t] = col4rows[t];
}

// ---------------------------------------------------------------------------
// 4) extrapolation + output write
// ---------------------------------------------------------------------------
__global__ void extrap_kernel(const float* __restrict__ p1_boxes,
                              const float* __restrict__ p1_logits,
                              const float* __restrict__ p2_boxes,
                              const float* __restrict__ p2_logits,
                              const float* __restrict__ toff,
                              float* __restrict__ out) {
    int idx = blockIdx.x * blockDim.x + threadIdx.x;
    const int boxTotal = BB * MM * 4;
    const int logTotal = BB * MM * CC;
    if (idx < boxTotal) {
        int d = idx & 3;
        int bi = idx >> 2;
        int b = bi / MM;
        float first  = toff[b * 3 + 1] - toff[b * 3 + 0];
        float second = toff[b * 3 + 2] - toff[b * 3 + 1];
        float factor = second / first;
        int mcol = g_map[bi];
        float b2 = p2_boxes[idx];
        float c1 = p1_boxes[(b * NN + mcol) * 4 + d];
        float val = b2 + (b2 - c1) * factor;
        if (d >= 2) val = fmaxf(val, 0.0f);
        out[idx] = val;
    } else if (idx < boxTotal + logTotal) {
        int t = idx - boxTotal;
        int c = t % CC;
        int bi = t / CC;
        int b = bi / MM;
        int mcol = g_map[bi];
        float l2 = p2_logits[t];
        float l1 = p1_logits[(b * NN + mcol) * CC + c];
        out[idx] = 0.5f * (l2 + l1);
    }
}

// ---------------------------------------------------------------------------
extern "C" void kernel_launch(void* const* d_in, const int* in_sizes, int n_in,
                              void* d_out, int out_size) {
    const float* p1_boxes  = (const float*)d_in[0];
    const float* p1_logits = (const float*)d_in[1];
    const float* p2_boxes  = (const float*)d_in[2];
    const float* p2_logits = (const float*)d_in[3];
    const float* toff      = (const float*)d_in[4];
    float* out = (float*)d_out;

    {
        int total = BB * NN * CC + BB * MM * CC;
        int threads = 256;
        int blocks = (total + threads - 1) / threads;
        sigmoid_kernel<<<blocks, threads>>>(p1_logits, p2_logits);
    }
    {
        dim3 grid(NPAD / 32, (MM + 31) / 32, BB);
        dim3 block(32, 32);
        cost_kernel<<<grid, block>>>(p1_boxes, p2_boxes);
    }
    lsa_kernel<<<BB, 32>>>();
    {
        int total = BB * MM * 4 + BB * MM * CC;
        int threads = 256;
        int blocks = (total + threads - 1) / threads;
        extrap_kernel<<<blocks, threads>>>(p1_boxes, p1_logits, p2_boxes,
                                           p2_logits, toff, out);
    }
}